// round 1
// baseline (speedup 1.0000x reference)
#include <cuda_runtime.h>
#include <math.h>

// Shapes fixed by the problem instance.
#define BB 4
#define LL 8192
#define DD 2048
#define BLT (BB * LL)          // 32768 rows
#define CAP (LL / 2)           // capacity = 4096
#define NOISE_SCALE 0.1f
#define AUX_W 0.01f
#define CAP_F 0.5f

// Scratch (no allocations allowed): noisy logits + per-batch sigmoid sums.
__device__ float  g_noisy[BLT];
__device__ double g_sums[BB];

// ---------------------------------------------------------------------------
// Kernel 0: zero the per-batch sigmoid accumulators.
// ---------------------------------------------------------------------------
__global__ void zero_sums_kernel() {
    if (threadIdx.x < BB) g_sums[threadIdx.x] = 0.0;
}

// ---------------------------------------------------------------------------
// Kernel 1: router matvec. 1 warp per row, 8 rows per 256-thread block.
//   out[BLT + row]   = logits (clean)
//   g_noisy[row]     = logits + noise*0.1
//   g_sums[b]       += sum of sigmoid(logits) over the block's 8 rows
// HBM-bound: streams 256 MB of x with float4 coalesced loads.
// ---------------------------------------------------------------------------
__global__ __launch_bounds__(256) void matvec_kernel(
    const float* __restrict__ x,
    const float* __restrict__ noise,
    const float* __restrict__ w,
    float* __restrict__ out)
{
    __shared__ float4 sw[DD / 4];     // 2048 floats = 8 KB
    __shared__ float  ssig[8];

    const int t = threadIdx.x;
    // stage w into smem (512 float4, 256 threads -> 2 each)
    const float4* w4 = reinterpret_cast<const float4*>(w);
    sw[t]       = w4[t];
    sw[t + 256] = w4[t + 256];
    __syncthreads();

    const int warp = t >> 5;
    const int lane = t & 31;
    const int row  = blockIdx.x * 8 + warp;

    const float4* xr = reinterpret_cast<const float4*>(x + (size_t)row * DD);
    float acc = 0.0f;
#pragma unroll
    for (int j = 0; j < 16; j++) {
        const float4 xv = __ldg(&xr[lane + 32 * j]);
        const float4 wv = sw[lane + 32 * j];
        acc = fmaf(xv.x, wv.x, acc);
        acc = fmaf(xv.y, wv.y, acc);
        acc = fmaf(xv.z, wv.z, acc);
        acc = fmaf(xv.w, wv.w, acc);
    }
#pragma unroll
    for (int o = 16; o; o >>= 1) acc += __shfl_down_sync(0xffffffffu, acc, o);

    if (lane == 0) {
        out[BLT + row] = acc;                               // clean logits
        g_noisy[row]   = fmaf(noise[row], NOISE_SCALE, acc); // noisy logits
        ssig[warp]     = 1.0f / (1.0f + expf(-acc));         // sigmoid
    }
    __syncthreads();
    if (t == 0) {
        float s = 0.0f;
#pragma unroll
        for (int i = 0; i < 8; i++) s += ssig[i];
        // all 8 rows of a block share one batch index (8192 % 8 == 0)
        atomicAdd(&g_sums[row / LL], (double)s);
    }
}

// ---------------------------------------------------------------------------
// Kernel 2: per-row exact top-CAP selection -> boolean mask (as 0.0/1.0).
// One block per row (grid = 4), 1024 threads, row keys resident in registers.
// k-th largest found by 32-step radix binary search on monotone uint keys.
// Ties at the threshold resolved toward lowest index (jax.lax.top_k order).
// ---------------------------------------------------------------------------
__global__ __launch_bounds__(1024) void select_kernel(float* __restrict__ out)
{
    __shared__ unsigned s_cnt;
    __shared__ unsigned s_prefix;
    __shared__ int      s_need;
    __shared__ int      s_eqn;
    __shared__ int      s_eqi[256];

    const int t   = threadIdx.x;
    const int row = blockIdx.x;
    const int EPT = LL / 1024;    // 8 elements per thread, contiguous by index

    unsigned mykeys[8];
#pragma unroll
    for (int j = 0; j < EPT; j++) {
        const int i = t * EPT + j;
        const unsigned b = __float_as_uint(g_noisy[row * LL + i]);
        // monotone map: float ordering -> unsigned ordering
        mykeys[j] = b ^ (((int)b >> 31) | 0x80000000u);
    }
    if (t == 0) { s_prefix = 0u; s_need = CAP; s_eqn = 0; }

    // radix binary search for the CAP-th largest key
    for (int bit = 31; bit >= 0; bit--) {
        __syncthreads();
        if (t == 0) s_cnt = 0u;
        __syncthreads();
        const unsigned target = (s_prefix >> bit) | 1u;
        int c = 0;
#pragma unroll
        for (int j = 0; j < EPT; j++) c += ((mykeys[j] >> bit) == target);
        c = __reduce_add_sync(0xffffffffu, c);
        if ((t & 31) == 0 && c) atomicAdd(&s_cnt, (unsigned)c);
        __syncthreads();
        if (t == 0) {
            if (s_need <= (int)s_cnt) s_prefix |= (1u << bit);
            else                      s_need   -= (int)s_cnt;
        }
    }
    __syncthreads();
    const unsigned thr = s_prefix;   // exact key value of the CAP-th largest

    // count strictly-greater, collect indices equal to threshold
    if (t == 0) s_cnt = 0u;
    __syncthreads();
    int cg = 0;
#pragma unroll
    for (int j = 0; j < EPT; j++) cg += (mykeys[j] > thr);
    cg = __reduce_add_sync(0xffffffffu, cg);
    if ((t & 31) == 0 && cg) atomicAdd(&s_cnt, (unsigned)cg);
#pragma unroll
    for (int j = 0; j < EPT; j++) {
        if (mykeys[j] == thr) {
            const int p = atomicAdd(&s_eqn, 1);
            if (p < 256) s_eqi[p] = t * EPT + j;
        }
    }
    __syncthreads();

    // write mask for strict-greater; equals get 0 for now
    float* m = out + row * LL;
#pragma unroll
    for (int j = 0; j < EPT; j++)
        m[t * EPT + j] = (mykeys[j] > thr) ? 1.0f : 0.0f;
    __syncthreads();

    // thread 0 promotes the lowest-index equal keys to fill exactly CAP slots
    if (t == 0) {
        int need = CAP - (int)s_cnt;
        const int n = (s_eqn < 256) ? s_eqn : 256;
        for (int sel = 0; sel < need; sel++) {
            int best = 0x7fffffff, bi = -1;
            for (int q = 0; q < n; q++) {
                if (s_eqi[q] >= 0 && s_eqi[q] < best) { best = s_eqi[q]; bi = q; }
            }
            if (bi < 0) break;
            m[best]   = 1.0f;
            s_eqi[bi] = -1;
        }
    }
}

// ---------------------------------------------------------------------------
// Kernel 3: aux load-balancing loss -> out[2*BLT]
// ---------------------------------------------------------------------------
__global__ void aux_kernel(float* __restrict__ out) {
    if (threadIdx.x == 0) {
        double a = 0.0;
        for (int b = 0; b < BB; b++) {
            const double d = g_sums[b] / (double)LL - (double)CAP_F;
            a += d * d;
        }
        out[2 * BLT] = (float)((double)AUX_W * a / (double)BB);
    }
}

// ---------------------------------------------------------------------------
extern "C" void kernel_launch(void* const* d_in, const int* in_sizes, int n_in,
                              void* d_out, int out_size)
{
    const float* x     = (const float*)d_in[0];  // [B, L, D]
    const float* noise = (const float*)d_in[1];  // [B, L]
    const float* w     = (const float*)d_in[2];  // [D]
    float* out = (float*)d_out;                  // [mask BL | logits BL | aux 1]

    (void)in_sizes; (void)n_in; (void)out_size;

    zero_sums_kernel<<<1, 32>>>();
    matvec_kernel<<<BLT / 8, 256>>>(x, noise, w, out);
    select_kernel<<<BB, 1024>>>(out);
    aux_kernel<<<1, 32>>>(out);
}